// round 13
// baseline (speedup 1.0000x reference)
#include <cuda_runtime.h>
#include <cuda_bf16.h>
#include <math.h>

// Problem constants (fixed by the reference)
#define BB 8
#define SS 4096
#define DD 1024
#define HH 16
#define HD 64
#define NR 32
#define NFREQ 32            // HD/2
#define ROWS (BB * SS * HH) // 524288
#define TPB 128
#define NCMAX 32            // max rotation chunks (worst case fully serial)

// Static device scratch
__device__ int    g_nc;
__device__ int    g_bad;
__device__ int4   g_sij[2 * NCMAX];   // chunk ch: (i0,j0,i1,j1) , (i2,j2,i3,j3)
__device__ float4 g_scs[2 * NCMAX];   // chunk ch: (c0,s0,c1,s1) , (c2,s2,c3,s3)

// ---------------------------------------------------------------------------
// Setup: identity check + rotation params + dependency-preserving schedule.
// Rotations on disjoint column pairs commute EXACTLY (even in FP), so packing
// them into disjoint chunks while preserving order among conflicting ones
// keeps the result bit-identical to the sequential scan.
__global__ void k_setup(const float* __restrict__ thetas,
                        const float* __restrict__ r_pairs,
                        const float* __restrict__ theta_scale,
                        const float* __restrict__ rm) {
    __shared__ int   si[NR], sj[NR];
    __shared__ float sc[NR], ss[NR];
    int t = threadIdx.x; // 256 threads
    int local = 0;
    const float4* __restrict__ rm4 = reinterpret_cast<const float4*>(rm);
    #pragma unroll
    for (int m = 0; m < 4; m++) {
        int e4 = t + m * 256;            // float4 index, 0..1023
        float4 v = __ldg(&rm4[e4]);
        int rrow = e4 >> 4, cc = (e4 & 15) << 2;
        if (v.x != ((rrow == cc + 0) ? 1.0f : 0.0f) ||
            v.y != ((rrow == cc + 1) ? 1.0f : 0.0f) ||
            v.z != ((rrow == cc + 2) ? 1.0f : 0.0f) ||
            v.w != ((rrow == cc + 3) ? 1.0f : 0.0f)) local = 1;
    }
    if (t < NR) {
        int i = (int)r_pairs[2 * t];
        int j = (int)r_pairs[2 * t + 1];
        si[t] = i; sj[t] = j;
        float th = thetas[t] * theta_scale[0];
        float sv, cv;
        sincosf(th, &sv, &cv);
        sc[t] = cv;
        ss[t] = (i == j) ? 0.0f : sv;    // makes the update branchless-exact
    }
    int bad = __syncthreads_or(local);
    if (t == 0) {
        g_bad = bad;
        // Greedy list scheduling into chunks of <=4 disjoint rotations.
        unsigned long long used[NCMAX];
        int cnt[NCMAX], lastc[HD];
        int ii[NCMAX][4], jj[NCMAX][4];
        float cv[NCMAX][4], sv[NCMAX][4];
        for (int ch = 0; ch < NCMAX; ch++) {
            used[ch] = 0ULL; cnt[ch] = 0;
            for (int k = 0; k < 4; k++) {     // null rotation = exact no-op
                ii[ch][k] = 0; jj[ch][k] = 0; cv[ch][k] = 1.0f; sv[ch][k] = 0.0f;
            }
        }
        for (int c = 0; c < HD; c++) lastc[c] = -1;
        int nc = 0;
        for (int r = 0; r < NR; r++) {
            int i = si[r], j = sj[r];
            int start = max(lastc[i], lastc[j]) + 1;  // after any conflicting rot
            int ch = start;
            while (cnt[ch] == 4 || ((used[ch] >> i) & 1ULL) || ((used[ch] >> j) & 1ULL)) ch++;
            int k = cnt[ch]++;
            ii[ch][k] = i; jj[ch][k] = j; cv[ch][k] = sc[r]; sv[ch][k] = ss[r];
            used[ch] |= (1ULL << i) | (1ULL << j);
            lastc[i] = ch; lastc[j] = ch;
            if (ch + 1 > nc) nc = ch + 1;
        }
        g_nc = nc;
        for (int ch = 0; ch < nc; ch++) {
            g_sij[2 * ch]     = make_int4(ii[ch][0], jj[ch][0], ii[ch][1], jj[ch][1]);
            g_sij[2 * ch + 1] = make_int4(ii[ch][2], jj[ch][2], ii[ch][3], jj[ch][3]);
            g_scs[2 * ch]     = make_float4(cv[ch][0], sv[ch][0], cv[ch][1], sv[ch][1]);
            g_scs[2 * ch + 1] = make_float4(cv[ch][2], sv[ch][2], cv[ch][3], sv[ch][3]);
        }
    }
}

// ---------------------------------------------------------------------------
// Compile-time XOR component permute: w[f] = v[f ^ P]
template<int P>
__device__ __forceinline__ float4 xperm_c(float4 v) {
    if constexpr (P == 0) return v;
    else if constexpr (P == 1) return make_float4(v.y, v.x, v.w, v.z);
    else if constexpr (P == 2) return make_float4(v.z, v.w, v.x, v.y);
    else                       return make_float4(v.w, v.z, v.y, v.x);
}

// Epilogue specialized on warp index W (compile-time permutes, no SELs).
template<int W>
__device__ __forceinline__ void epilogue(const float4* __restrict__ buf4,
                                         const float4 (*__restrict__ cosq)[8],
                                         const float4 (*__restrict__ sinq)[8],
                                         float4* __restrict__ op,
                                         int sub, int qp) {
    #pragma unroll
    for (int it = 0; it < 8; it++) {
        int row  = it * 16 + sub * 4 + W;
        int base = row * 16;
        int qA   = (2 * qp) ^ sub ^ (4 * (it & 1)); // phys quad of col 8qp
        float4 ra = buf4[base + qA];
        float4 rb = buf4[base + (qA ^ 1)];
        float4 ya = xperm_c<W>(ra);       // y[8qp+0 .. 8qp+3]
        float4 yb = xperm_c<W>(rb);       // y[8qp+4 .. 8qp+7]
        float4 cq = cosq[it][qp];         // s-position = it (uniform)
        float4 sq = sinq[it][qp];

        float4 lo, hi;                    // freqs k = 4qp..4qp+3
        lo.x = fmaf(ya.x, cq.x, -ya.y * sq.x);
        lo.y = fmaf(ya.z, cq.y, -ya.w * sq.y);
        lo.z = fmaf(yb.x, cq.z, -yb.y * sq.z);
        lo.w = fmaf(yb.z, cq.w, -yb.w * sq.w);
        hi.x = fmaf(ya.x, sq.x,  ya.y * cq.x);
        hi.y = fmaf(ya.z, sq.y,  ya.w * cq.y);
        hi.z = fmaf(yb.x, sq.z,  yb.y * cq.z);
        hi.w = fmaf(yb.z, sq.w,  yb.w * cq.w);

        __stcs(&op[base + qp], lo);       // out cols 4qp..4qp+3
        __stcs(&op[base + 8 + qp], hi);   // out cols 32+4qp..32+4qp+3
    }
}

// Main kernel. 128 threads/block, 128 rows (32 KB). Swizzled layout:
// element (row, col) at buf[row*64 + (col ^ (row & 31))].
__global__ void __launch_bounds__(TPB, 6)
k_main(const float* __restrict__ x,
       const float* __restrict__ r_matrix,
       const float* __restrict__ inv_freq,
       float* __restrict__ out) {
    __shared__ float  buf[TPB * HD];      // 32 KB, swizzled
    __shared__ float4 cosq[8][8];         // [s-pos][freq-quad]
    __shared__ float4 sinq[8][8];
    __shared__ int4   ssij[2 * NCMAX];    // 1 KB
    __shared__ float4 sscs[2 * NCMAX];    // 1 KB
    __shared__ int    s_nc;

    const int tid = threadIdx.x;
    const int bid = blockIdx.x;
    const long long elem_base = (long long)bid * (TPB * HD);
    float4* __restrict__ buf4 = reinterpret_cast<float4*>(buf);

    const float4* __restrict__ xin = reinterpret_cast<const float4*>(x) + (elem_base >> 2);
    const int prow = tid >> 4;
    const int c0   = (tid & 15) << 2;

    // ---- chunk 0 loads issued FIRST (4 LDG.128) ----
    float4 v0[4];
    #pragma unroll
    for (int u = 0; u < 4; u++) v0[u] = __ldcs(&xin[tid + u * TPB]);

    // ---- fill chunk-0 load latency: schedule copy + cs tables ----
    if (tid == 0) s_nc = g_nc;
    if (tid < 2 * NCMAX) {                // 64 threads
        ssij[tid] = g_sij[tid];
        sscs[tid] = g_scs[tid];
    }
    {
        int sg0 = bid * 8;
        #pragma unroll
        for (int e = tid; e < 8 * NFREQ; e += TPB) {
            int l = e >> 5, k = e & 31;
            int s = (sg0 + l) & (SS - 1);
            float a = (float)s * __ldg(&inv_freq[k]);
            float sv, cv;
            sincosf(a, &sv, &cv);
            reinterpret_cast<float*>(&cosq[l][k >> 2])[k & 3] = cv;
            reinterpret_cast<float*>(&sinq[l][k >> 2])[k & 3] = sv;
        }
    }
    const int bad = __ldg(&g_bad);

    // ---- store chunk 0, then stream chunks 1..3 (MLP_p1 capped at 4) ----
    #pragma unroll
    for (int u = 0; u < 4; u++) {
        int row = prow + u * 8;
        float* bp = &buf[row * 64];
        int rx = row & 31;
        bp[(c0 + 0) ^ rx] = v0[u].x;
        bp[(c0 + 1) ^ rx] = v0[u].y;
        bp[(c0 + 2) ^ rx] = v0[u].z;
        bp[(c0 + 3) ^ rx] = v0[u].w;
    }
    asm volatile("" ::: "memory");
    #pragma unroll
    for (int ch = 1; ch < 4; ch++) {
        float4 v[4];
        #pragma unroll
        for (int u = 0; u < 4; u++)
            v[u] = __ldcs(&xin[tid + (ch * 4 + u) * TPB]);
        #pragma unroll
        for (int u = 0; u < 4; u++) {
            int it  = ch * 4 + u;
            int row = prow + it * 8;
            float* bp = &buf[row * 64];
            int rx = row & 31;
            bp[(c0 + 0) ^ rx] = v[u].x;
            bp[(c0 + 1) ^ rx] = v[u].y;
            bp[(c0 + 2) ^ rx] = v[u].z;
            bp[(c0 + 3) ^ rx] = v[u].w;
        }
        asm volatile("" ::: "memory");
    }
    __syncthreads();

    // --- Givens rotations, chunked: 8 independent LDS -> FMA -> 8 STS.
    //     ~9 chunks instead of a 32-step serial dependency chain. ---
    {
        float* __restrict__ my = &buf[tid * HD];
        const int rsw = tid & 31;
        const int nc = s_nc;
        for (int ch = 0; ch < nc; ch++) {
            int4   p0 = ssij[2 * ch], p1 = ssij[2 * ch + 1];
            float4 q0 = sscs[2 * ch], q1 = sscs[2 * ch + 1];
            float xi0 = my[p0.x ^ rsw], xj0 = my[p0.y ^ rsw];
            float xi1 = my[p0.z ^ rsw], xj1 = my[p0.w ^ rsw];
            float xi2 = my[p1.x ^ rsw], xj2 = my[p1.y ^ rsw];
            float xi3 = my[p1.z ^ rsw], xj3 = my[p1.w ^ rsw];
            my[p0.x ^ rsw] = fmaf(q0.y, xj0,  q0.x * xi0);
            my[p0.y ^ rsw] = fmaf(q0.x, xj0, -q0.y * xi0);
            my[p0.z ^ rsw] = fmaf(q0.w, xj1,  q0.z * xi1);
            my[p0.w ^ rsw] = fmaf(q0.z, xj1, -q0.w * xi1);
            my[p1.x ^ rsw] = fmaf(q1.y, xj2,  q1.x * xi2);
            my[p1.y ^ rsw] = fmaf(q1.x, xj2, -q1.y * xi2);
            my[p1.z ^ rsw] = fmaf(q1.w, xj3,  q1.z * xi3);
            my[p1.w ^ rsw] = fmaf(q1.z, xj3, -q1.w * xi3);
        }
    }

    // --- cold generic path: y = y @ r_matrix (own row only, no barrier) ---
    if (bad) {
        const int rbase = tid * HD;
        const int rsw   = tid & 31;
        float zl[HD]; // local memory (unroll 1) -> no hot-path registers
        #pragma unroll 1
        for (int c = 0; c < HD; c++) {
            float acc = 0.0f;
            #pragma unroll 1
            for (int k = 0; k < HD; k++)
                acc = fmaf(buf[rbase + (k ^ rsw)], __ldg(&r_matrix[k * HD + c]), acc);
            zl[c] = acc;
        }
        #pragma unroll 1
        for (int c = 0; c < HD; c++)
            buf[rbase + (c ^ rsw)] = zl[c];
    }
    __syncthreads();

    // --- fused RoPE + store, specialized per warp (uniform switch) ---
    float4* __restrict__ op = reinterpret_cast<float4*>(out) + (elem_base >> 2);
    {
        const int l5  = tid & 31;
        const int sub = l5 >> 3;          // 0..3
        const int qp  = l5 & 7;           // freq-quad 0..7
        switch (tid >> 5) {
            case 0: epilogue<0>(buf4, cosq, sinq, op, sub, qp); break;
            case 1: epilogue<1>(buf4, cosq, sinq, op, sub, qp); break;
            case 2: epilogue<2>(buf4, cosq, sinq, op, sub, qp); break;
            default: epilogue<3>(buf4, cosq, sinq, op, sub, qp); break;
        }
    }
}

// ---------------------------------------------------------------------------
extern "C" void kernel_launch(void* const* d_in, const int* in_sizes, int n_in,
                              void* d_out, int out_size) {
    const float* x        = (const float*)d_in[0];
    const float* thetas   = (const float*)d_in[1];
    const float* r_pairs  = (const float*)d_in[2];
    const float* t_scale  = (const float*)d_in[3];
    // d_in[4] = n_rots_scale (unused by the reference)
    const float* r_matrix = (const float*)d_in[5];
    const float* inv_freq = (const float*)d_in[6];
    float* out = (float*)d_out;

    k_setup<<<1, 256>>>(thetas, r_pairs, t_scale, r_matrix);

    int nblocks = ROWS / TPB; // 4096
    k_main<<<nblocks, TPB>>>(x, r_matrix, inv_freq, out);
}

// round 14
// speedup vs baseline: 1.0661x; 1.0661x over previous
#include <cuda_runtime.h>
#include <cuda_bf16.h>
#include <math.h>

// Problem constants (fixed by the reference)
#define BB 8
#define SS 4096
#define DD 1024
#define HH 16
#define HD 64
#define NR 32
#define NFREQ 32            // HD/2
#define ROWS (BB * SS * HH) // 524288
#define TPB 128
#define NCMAX 32            // max rotation chunks (worst case fully serial)

// Static device scratch. Flat, 16B-aligned: chunk ch occupies entries
// [ch*8, ch*8+8): (i0,j0,i1,j1,i2,j2,i3,j3) / (c0,s0,c1,s1,c2,s2,c3,s3).
__device__ int    g_nc;
__device__ int    g_bad;
__device__ __align__(16) int   g_pair[NCMAX * 8];
__device__ __align__(16) float g_csab[NCMAX * 8];

// ---------------------------------------------------------------------------
// Setup: identity check + warp-cooperative rotation scheduling.
// Rotations on disjoint column pairs commute EXACTLY; Kahn layering with
// ballots assigns each rotation the earliest level after all its conflicts,
// then packs each level (mutually disjoint by construction) into chunks of 4.
// Bit-identical to the sequential scan.
__global__ void k_setup(const float* __restrict__ thetas,
                        const float* __restrict__ r_pairs,
                        const float* __restrict__ theta_scale,
                        const float* __restrict__ rm) {
    __shared__ int   si[NR], sj[NR];
    __shared__ int   scnt[NR];     // rotations per level
    __shared__ int   sbase[NR];    // first chunk of level
    int t = threadIdx.x; // 256 threads

    // identity check (all threads, 16KB)
    int local = 0;
    const float4* __restrict__ rm4 = reinterpret_cast<const float4*>(rm);
    #pragma unroll
    for (int m = 0; m < 4; m++) {
        int e4 = t + m * 256;            // float4 index, 0..1023
        float4 v = __ldg(&rm4[e4]);
        int rrow = e4 >> 4, cc = (e4 & 15) << 2;
        if (v.x != ((rrow == cc + 0) ? 1.0f : 0.0f) ||
            v.y != ((rrow == cc + 1) ? 1.0f : 0.0f) ||
            v.z != ((rrow == cc + 2) ? 1.0f : 0.0f) ||
            v.w != ((rrow == cc + 3) ? 1.0f : 0.0f)) local = 1;
    }
    int bad = __syncthreads_or(local);
    if (t == 0) g_bad = bad;

    // null-init schedule (exact no-op rotations: i=j=0, c=1, s=0)
    g_pair[t] = 0;
    g_csab[t] = (t & 1) ? 0.0f : 1.0f;

    // rotation params
    int i = 0, j = 0;
    float cv = 1.0f, sv = 0.0f;
    if (t < NR) {
        i = (int)r_pairs[2 * t];
        j = (int)r_pairs[2 * t + 1];
        float th = thetas[t] * theta_scale[0];
        float s_, c_;
        sincosf(th, &s_, &c_);
        cv = c_;
        sv = (i == j) ? 0.0f : s_;   // branchless-exact degenerate case
        si[t] = i; sj[t] = j;
    }
    __syncthreads();   // si/sj visible + global null-init ordered before writes

    if (t < 32) {      // warp 0 does the scheduling
        // conflict mask over earlier rotations
        unsigned conf = 0;
        #pragma unroll
        for (int r = 0; r < NR; r++) {
            int ci = si[r], cj = sj[r];
            bool hit = (ci == i) | (ci == j) | (cj == i) | (cj == j);
            if (r < t && hit) conf |= (1u << r);
        }
        // Kahn layering with ballots (earliest remaining rot always ready)
        unsigned remaining = 0xFFFFFFFFu;
        int mylevel = 0, myrank = 0, level = 0;
        while (remaining) {
            bool ready = ((remaining >> t) & 1u) && ((conf & remaining) == 0u);
            unsigned bal = __ballot_sync(0xFFFFFFFFu, ready);
            if (ready) {
                mylevel = level;
                myrank  = __popc(bal & ((1u << t) - 1u));
            }
            if (t == 0) scnt[level] = __popc(bal);
            remaining &= ~bal;
            level++;
        }
        __syncwarp();
        if (t == 0) {
            int b = 0;
            for (int l = 0; l < level; l++) {
                sbase[l] = b;
                b += (scnt[l] + 3) >> 2;   // chunks of 4 per level
            }
            g_nc = b;
        }
        __syncwarp();
        int ch   = sbase[mylevel] + (myrank >> 2);
        int slot = myrank & 3;
        g_pair[ch * 8 + 2 * slot]     = i;
        g_pair[ch * 8 + 2 * slot + 1] = j;
        g_csab[ch * 8 + 2 * slot]     = cv;
        g_csab[ch * 8 + 2 * slot + 1] = sv;
    }
}

// ---------------------------------------------------------------------------
// Compile-time XOR component permute: w[f] = v[f ^ P]
template<int P>
__device__ __forceinline__ float4 xperm_c(float4 v) {
    if constexpr (P == 0) return v;
    else if constexpr (P == 1) return make_float4(v.y, v.x, v.w, v.z);
    else if constexpr (P == 2) return make_float4(v.z, v.w, v.x, v.y);
    else                       return make_float4(v.w, v.z, v.y, v.x);
}

// Epilogue specialized on warp index W (compile-time permutes, no SELs).
template<int W>
__device__ __forceinline__ void epilogue(const float4* __restrict__ buf4,
                                         const float4 (*__restrict__ cosq)[8],
                                         const float4 (*__restrict__ sinq)[8],
                                         float4* __restrict__ op,
                                         int sub, int qp) {
    #pragma unroll
    for (int it = 0; it < 8; it++) {
        int row  = it * 16 + sub * 4 + W;
        int base = row * 16;
        int qA   = (2 * qp) ^ sub ^ (4 * (it & 1)); // phys quad of col 8qp
        float4 ra = buf4[base + qA];
        float4 rb = buf4[base + (qA ^ 1)];
        float4 ya = xperm_c<W>(ra);       // y[8qp+0 .. 8qp+3]
        float4 yb = xperm_c<W>(rb);       // y[8qp+4 .. 8qp+7]
        float4 cq = cosq[it][qp];         // s-position = it (uniform)
        float4 sq = sinq[it][qp];

        float4 lo, hi;                    // freqs k = 4qp..4qp+3
        lo.x = fmaf(ya.x, cq.x, -ya.y * sq.x);
        lo.y = fmaf(ya.z, cq.y, -ya.w * sq.y);
        lo.z = fmaf(yb.x, cq.z, -yb.y * sq.z);
        lo.w = fmaf(yb.z, cq.w, -yb.w * sq.w);
        hi.x = fmaf(ya.x, sq.x,  ya.y * cq.x);
        hi.y = fmaf(ya.z, sq.y,  ya.w * cq.y);
        hi.z = fmaf(yb.x, sq.z,  yb.y * cq.z);
        hi.w = fmaf(yb.z, sq.w,  yb.w * cq.w);

        __stcs(&op[base + qp], lo);       // out cols 4qp..4qp+3
        __stcs(&op[base + 8 + qp], hi);   // out cols 32+4qp..32+4qp+3
    }
}

// Main kernel. 128 threads/block, 128 rows (32 KB). Swizzled layout:
// element (row, col) at buf[row*64 + (col ^ (row & 31))].
__global__ void __launch_bounds__(TPB, 6)
k_main(const float* __restrict__ x,
       const float* __restrict__ r_matrix,
       const float* __restrict__ inv_freq,
       float* __restrict__ out) {
    __shared__ float  buf[TPB * HD];      // 32 KB, swizzled
    __shared__ float4 cosq[8][8];         // [s-pos][freq-quad]
    __shared__ float4 sinq[8][8];
    __shared__ int4   ssij[2 * NCMAX];    // 1 KB
    __shared__ float4 sscs[2 * NCMAX];    // 1 KB
    __shared__ int    s_nc;

    const int tid = threadIdx.x;
    const int bid = blockIdx.x;
    const long long elem_base = (long long)bid * (TPB * HD);
    float4* __restrict__ buf4 = reinterpret_cast<float4*>(buf);

    const float4* __restrict__ xin = reinterpret_cast<const float4*>(x) + (elem_base >> 2);
    const int prow = tid >> 4;
    const int c0   = (tid & 15) << 2;

    // ---- chunk 0 loads issued FIRST (4 LDG.128) ----
    float4 v0[4];
    #pragma unroll
    for (int u = 0; u < 4; u++) v0[u] = __ldcs(&xin[tid + u * TPB]);

    // ---- fill chunk-0 load latency: schedule copy + cs tables ----
    if (tid == 0) s_nc = g_nc;
    if (tid < 2 * NCMAX) {                // 64 threads
        ssij[tid] = reinterpret_cast<const int4*>(g_pair)[tid];
        sscs[tid] = reinterpret_cast<const float4*>(g_csab)[tid];
    }
    {
        int sg0 = bid * 8;
        #pragma unroll
        for (int e = tid; e < 8 * NFREQ; e += TPB) {
            int l = e >> 5, k = e & 31;
            int s = (sg0 + l) & (SS - 1);
            float a = (float)s * __ldg(&inv_freq[k]);
            float sv, cv;
            sincosf(a, &sv, &cv);
            reinterpret_cast<float*>(&cosq[l][k >> 2])[k & 3] = cv;
            reinterpret_cast<float*>(&sinq[l][k >> 2])[k & 3] = sv;
        }
    }
    const int bad = __ldg(&g_bad);

    // ---- store chunk 0, then stream chunks 1..3 (MLP_p1 capped at 4) ----
    #pragma unroll
    for (int u = 0; u < 4; u++) {
        int row = prow + u * 8;
        float* bp = &buf[row * 64];
        int rx = row & 31;
        bp[(c0 + 0) ^ rx] = v0[u].x;
        bp[(c0 + 1) ^ rx] = v0[u].y;
        bp[(c0 + 2) ^ rx] = v0[u].z;
        bp[(c0 + 3) ^ rx] = v0[u].w;
    }
    asm volatile("" ::: "memory");
    #pragma unroll
    for (int ch = 1; ch < 4; ch++) {
        float4 v[4];
        #pragma unroll
        for (int u = 0; u < 4; u++)
            v[u] = __ldcs(&xin[tid + (ch * 4 + u) * TPB]);
        #pragma unroll
        for (int u = 0; u < 4; u++) {
            int it  = ch * 4 + u;
            int row = prow + it * 8;
            float* bp = &buf[row * 64];
            int rx = row & 31;
            bp[(c0 + 0) ^ rx] = v[u].x;
            bp[(c0 + 1) ^ rx] = v[u].y;
            bp[(c0 + 2) ^ rx] = v[u].z;
            bp[(c0 + 3) ^ rx] = v[u].w;
        }
        asm volatile("" ::: "memory");
    }
    __syncthreads();

    // --- Givens rotations, chunked: 8 independent LDS -> FMA -> 8 STS.
    //     ~6-9 chunks instead of a 32-step serial dependency chain. ---
    {
        float* __restrict__ my = &buf[tid * HD];
        const int rsw = tid & 31;
        const int nc = s_nc;
        for (int ch = 0; ch < nc; ch++) {
            int4   p0 = ssij[2 * ch], p1 = ssij[2 * ch + 1];
            float4 q0 = sscs[2 * ch], q1 = sscs[2 * ch + 1];
            float xi0 = my[p0.x ^ rsw], xj0 = my[p0.y ^ rsw];
            float xi1 = my[p0.z ^ rsw], xj1 = my[p0.w ^ rsw];
            float xi2 = my[p1.x ^ rsw], xj2 = my[p1.y ^ rsw];
            float xi3 = my[p1.z ^ rsw], xj3 = my[p1.w ^ rsw];
            my[p0.x ^ rsw] = fmaf(q0.y, xj0,  q0.x * xi0);
            my[p0.y ^ rsw] = fmaf(q0.x, xj0, -q0.y * xi0);
            my[p0.z ^ rsw] = fmaf(q0.w, xj1,  q0.z * xi1);
            my[p0.w ^ rsw] = fmaf(q0.z, xj1, -q0.w * xi1);
            my[p1.x ^ rsw] = fmaf(q1.y, xj2,  q1.x * xi2);
            my[p1.y ^ rsw] = fmaf(q1.x, xj2, -q1.y * xi2);
            my[p1.z ^ rsw] = fmaf(q1.w, xj3,  q1.z * xi3);
            my[p1.w ^ rsw] = fmaf(q1.z, xj3, -q1.w * xi3);
        }
    }

    // --- cold generic path: y = y @ r_matrix (own row only, no barrier) ---
    if (bad) {
        const int rbase = tid * HD;
        const int rsw   = tid & 31;
        float zl[HD]; // local memory (unroll 1) -> no hot-path registers
        #pragma unroll 1
        for (int c = 0; c < HD; c++) {
            float acc = 0.0f;
            #pragma unroll 1
            for (int k = 0; k < HD; k++)
                acc = fmaf(buf[rbase + (k ^ rsw)], __ldg(&r_matrix[k * HD + c]), acc);
            zl[c] = acc;
        }
        #pragma unroll 1
        for (int c = 0; c < HD; c++)
            buf[rbase + (c ^ rsw)] = zl[c];
    }
    __syncthreads();

    // --- fused RoPE + store, specialized per warp (uniform switch) ---
    float4* __restrict__ op = reinterpret_cast<float4*>(out) + (elem_base >> 2);
    {
        const int l5  = tid & 31;
        const int sub = l5 >> 3;          // 0..3
        const int qp  = l5 & 7;           // freq-quad 0..7
        switch (tid >> 5) {
            case 0: epilogue<0>(buf4, cosq, sinq, op, sub, qp); break;
            case 1: epilogue<1>(buf4, cosq, sinq, op, sub, qp); break;
            case 2: epilogue<2>(buf4, cosq, sinq, op, sub, qp); break;
            default: epilogue<3>(buf4, cosq, sinq, op, sub, qp); break;
        }
    }
}

// ---------------------------------------------------------------------------
extern "C" void kernel_launch(void* const* d_in, const int* in_sizes, int n_in,
                              void* d_out, int out_size) {
    const float* x        = (const float*)d_in[0];
    const float* thetas   = (const float*)d_in[1];
    const float* r_pairs  = (const float*)d_in[2];
    const float* t_scale  = (const float*)d_in[3];
    // d_in[4] = n_rots_scale (unused by the reference)
    const float* r_matrix = (const float*)d_in[5];
    const float* inv_freq = (const float*)d_in[6];
    float* out = (float*)d_out;

    k_setup<<<1, 256>>>(thetas, r_pairs, t_scale, r_matrix);

    int nblocks = ROWS / TPB; // 4096
    k_main<<<nblocks, TPB>>>(x, r_matrix, inv_freq, out);
}

// round 16
// speedup vs baseline: 1.1026x; 1.0342x over previous
#include <cuda_runtime.h>
#include <cuda_bf16.h>
#include <math.h>

// Problem constants (fixed by the reference)
#define BB 8
#define SS 4096
#define DD 1024
#define HH 16
#define HD 64
#define NR 32
#define NFREQ 32            // HD/2
#define ROWS (BB * SS * HH) // 524288
#define TPB 128
#define NCMAX 32            // max rotation chunks (worst case fully serial)

// Static device scratch. Flat, 16B-aligned: chunk ch occupies entries
// [ch*8, ch*8+8): (i0,j0,i1,j1,i2,j2,i3,j3) / (c0,s0,c1,s1,c2,s2,c3,s3).
__device__ int    g_nc;
__device__ int    g_bad;
__device__ __align__(16) int   g_pair[NCMAX * 8];
__device__ __align__(16) float g_csab[NCMAX * 8];

// ---------------------------------------------------------------------------
// Setup: identity check + warp-cooperative rotation scheduling.
// Rotations on disjoint column pairs commute EXACTLY. Capacity-capped Kahn:
// each iteration selects up to 4 READY rotations (all conflicts placed in
// earlier chunks) by rank. The ready set is always column-disjoint (two
// rotations sharing a column are conflict-ordered), and conflicting pairs
// land in order in different chunks -> bit-identical to the sequential scan.
// Near-minimal chunk count (~NR/4) with padding only in blocked tails.
__global__ void k_setup(const float* __restrict__ thetas,
                        const float* __restrict__ r_pairs,
                        const float* __restrict__ theta_scale,
                        const float* __restrict__ rm) {
    __shared__ int si[NR], sj[NR];
    int t = threadIdx.x; // 256 threads

    // identity check (all threads, 16KB)
    int local = 0;
    const float4* __restrict__ rm4 = reinterpret_cast<const float4*>(rm);
    #pragma unroll
    for (int m = 0; m < 4; m++) {
        int e4 = t + m * 256;            // float4 index, 0..1023
        float4 v = __ldg(&rm4[e4]);
        int rrow = e4 >> 4, cc = (e4 & 15) << 2;
        if (v.x != ((rrow == cc + 0) ? 1.0f : 0.0f) ||
            v.y != ((rrow == cc + 1) ? 1.0f : 0.0f) ||
            v.z != ((rrow == cc + 2) ? 1.0f : 0.0f) ||
            v.w != ((rrow == cc + 3) ? 1.0f : 0.0f)) local = 1;
    }
    int bad = __syncthreads_or(local);
    if (t == 0) g_bad = bad;

    // null-init schedule (exact no-op rotations: i=j=0, c=1, s=0)
    g_pair[t] = 0;
    g_csab[t] = (t & 1) ? 0.0f : 1.0f;

    // rotation params
    int i = 0, j = 0;
    float cv = 1.0f, sv = 0.0f;
    if (t < NR) {
        i = (int)r_pairs[2 * t];
        j = (int)r_pairs[2 * t + 1];
        float th = thetas[t] * theta_scale[0];
        float s_, c_;
        sincosf(th, &s_, &c_);
        cv = c_;
        sv = (i == j) ? 0.0f : s_;   // branchless-exact degenerate case
        si[t] = i; sj[t] = j;
    }
    __syncthreads();   // si/sj visible + global null-init ordered before writes

    if (t < 32) {      // warp 0 does the scheduling
        // conflict mask over earlier rotations sharing a column
        unsigned conf = 0;
        #pragma unroll
        for (int r = 0; r < NR; r++) {
            int ci = si[r], cj = sj[r];
            bool hit = (ci == i) | (ci == j) | (cj == i) | (cj == j);
            if (r < t && hit) conf |= (1u << r);
        }
        // capacity-capped Kahn: <=4 ready rotations per chunk, lowest rank
        unsigned remaining = 0xFFFFFFFFu;
        int mych = 0, myslot = 0, ch = 0;
        while (remaining) {
            bool ready = ((remaining >> t) & 1u) && ((conf & remaining) == 0u);
            unsigned bal = __ballot_sync(0xFFFFFFFFu, ready);
            int rank = __popc(bal & ((1u << t) - 1u));
            bool sel = ready && (rank < 4);
            unsigned selb = __ballot_sync(0xFFFFFFFFu, sel);
            if (sel) { mych = ch; myslot = rank; }
            remaining &= ~selb;
            ch++;
        }
        if (t == 0) g_nc = ch;
        g_pair[mych * 8 + 2 * myslot]     = i;
        g_pair[mych * 8 + 2 * myslot + 1] = j;
        g_csab[mych * 8 + 2 * myslot]     = cv;
        g_csab[mych * 8 + 2 * myslot + 1] = sv;
    }
}

// ---------------------------------------------------------------------------
// Compile-time XOR component permute: w[f] = v[f ^ P]
template<int P>
__device__ __forceinline__ float4 xperm_c(float4 v) {
    if constexpr (P == 0) return v;
    else if constexpr (P == 1) return make_float4(v.y, v.x, v.w, v.z);
    else if constexpr (P == 2) return make_float4(v.z, v.w, v.x, v.y);
    else                       return make_float4(v.w, v.z, v.y, v.x);
}

// Epilogue specialized on warp index W (compile-time permutes, no SELs).
template<int W>
__device__ __forceinline__ void epilogue(const float4* __restrict__ buf4,
                                         const float4 (*__restrict__ cosq)[8],
                                         const float4 (*__restrict__ sinq)[8],
                                         float4* __restrict__ op,
                                         int sub, int qp) {
    #pragma unroll
    for (int it = 0; it < 8; it++) {
        int row  = it * 16 + sub * 4 + W;
        int base = row * 16;
        int qA   = (2 * qp) ^ sub ^ (4 * (it & 1)); // phys quad of col 8qp
        float4 ra = buf4[base + qA];
        float4 rb = buf4[base + (qA ^ 1)];
        float4 ya = xperm_c<W>(ra);       // y[8qp+0 .. 8qp+3]
        float4 yb = xperm_c<W>(rb);       // y[8qp+4 .. 8qp+7]
        float4 cq = cosq[it][qp];         // s-position = it (uniform)
        float4 sq = sinq[it][qp];

        float4 lo, hi;                    // freqs k = 4qp..4qp+3
        lo.x = fmaf(ya.x, cq.x, -ya.y * sq.x);
        lo.y = fmaf(ya.z, cq.y, -ya.w * sq.y);
        lo.z = fmaf(yb.x, cq.z, -yb.y * sq.z);
        lo.w = fmaf(yb.z, cq.w, -yb.w * sq.w);
        hi.x = fmaf(ya.x, sq.x,  ya.y * cq.x);
        hi.y = fmaf(ya.z, sq.y,  ya.w * cq.y);
        hi.z = fmaf(yb.x, sq.z,  yb.y * cq.z);
        hi.w = fmaf(yb.z, sq.w,  yb.w * cq.w);

        __stcs(&op[base + qp], lo);       // out cols 4qp..4qp+3
        __stcs(&op[base + 8 + qp], hi);   // out cols 32+4qp..32+4qp+3
    }
}

// Main kernel. 128 threads/block, 128 rows (32 KB). Swizzled layout:
// element (row, col) at buf[row*64 + (col ^ (row & 31))].
__global__ void __launch_bounds__(TPB, 6)
k_main(const float* __restrict__ x,
       const float* __restrict__ r_matrix,
       const float* __restrict__ inv_freq,
       float* __restrict__ out) {
    __shared__ float  buf[TPB * HD];      // 32 KB, swizzled
    __shared__ float4 cosq[8][8];         // [s-pos][freq-quad]
    __shared__ float4 sinq[8][8];
    __shared__ int4   ssij[2 * NCMAX];    // 1 KB
    __shared__ float4 sscs[2 * NCMAX];    // 1 KB
    __shared__ int    s_nc;

    const int tid = threadIdx.x;
    const int bid = blockIdx.x;
    const long long elem_base = (long long)bid * (TPB * HD);
    float4* __restrict__ buf4 = reinterpret_cast<float4*>(buf);

    const float4* __restrict__ xin = reinterpret_cast<const float4*>(x) + (elem_base >> 2);
    const int prow = tid >> 4;
    const int c0   = (tid & 15) << 2;

    // ---- chunk 0 loads issued FIRST (4 LDG.128) ----
    float4 v0[4];
    #pragma unroll
    for (int u = 0; u < 4; u++) v0[u] = __ldcs(&xin[tid + u * TPB]);

    // ---- fill chunk-0 load latency: schedule copy + cs tables ----
    if (tid == 0) s_nc = g_nc;
    if (tid < 2 * NCMAX) {                // 64 threads
        ssij[tid] = reinterpret_cast<const int4*>(g_pair)[tid];
        sscs[tid] = reinterpret_cast<const float4*>(g_csab)[tid];
    }
    {
        int sg0 = bid * 8;
        #pragma unroll
        for (int e = tid; e < 8 * NFREQ; e += TPB) {
            int l = e >> 5, k = e & 31;
            int s = (sg0 + l) & (SS - 1);
            float a = (float)s * __ldg(&inv_freq[k]);
            float sv, cv;
            sincosf(a, &sv, &cv);
            reinterpret_cast<float*>(&cosq[l][k >> 2])[k & 3] = cv;
            reinterpret_cast<float*>(&sinq[l][k >> 2])[k & 3] = sv;
        }
    }
    const int bad = __ldg(&g_bad);

    // ---- store chunk 0, then stream chunks 1..3 (MLP_p1 capped at 4) ----
    #pragma unroll
    for (int u = 0; u < 4; u++) {
        int row = prow + u * 8;
        float* bp = &buf[row * 64];
        int rx = row & 31;
        bp[(c0 + 0) ^ rx] = v0[u].x;
        bp[(c0 + 1) ^ rx] = v0[u].y;
        bp[(c0 + 2) ^ rx] = v0[u].z;
        bp[(c0 + 3) ^ rx] = v0[u].w;
    }
    asm volatile("" ::: "memory");
    #pragma unroll
    for (int ch = 1; ch < 4; ch++) {
        float4 v[4];
        #pragma unroll
        for (int u = 0; u < 4; u++)
            v[u] = __ldcs(&xin[tid + (ch * 4 + u) * TPB]);
        #pragma unroll
        for (int u = 0; u < 4; u++) {
            int it  = ch * 4 + u;
            int row = prow + it * 8;
            float* bp = &buf[row * 64];
            int rx = row & 31;
            bp[(c0 + 0) ^ rx] = v[u].x;
            bp[(c0 + 1) ^ rx] = v[u].y;
            bp[(c0 + 2) ^ rx] = v[u].z;
            bp[(c0 + 3) ^ rx] = v[u].w;
        }
        asm volatile("" ::: "memory");
    }
    __syncthreads();

    // --- Givens rotations, chunked: 8 independent LDS -> FMA -> 8 STS.
    //     ~8 chunks (near-minimal packing) vs 32-step serial chain. ---
    {
        float* __restrict__ my = &buf[tid * HD];
        const int rsw = tid & 31;
        const int nc = s_nc;
        for (int ch = 0; ch < nc; ch++) {
            int4   p0 = ssij[2 * ch], p1 = ssij[2 * ch + 1];
            float4 q0 = sscs[2 * ch], q1 = sscs[2 * ch + 1];
            float xi0 = my[p0.x ^ rsw], xj0 = my[p0.y ^ rsw];
            float xi1 = my[p0.z ^ rsw], xj1 = my[p0.w ^ rsw];
            float xi2 = my[p1.x ^ rsw], xj2 = my[p1.y ^ rsw];
            float xi3 = my[p1.z ^ rsw], xj3 = my[p1.w ^ rsw];
            my[p0.x ^ rsw] = fmaf(q0.y, xj0,  q0.x * xi0);
            my[p0.y ^ rsw] = fmaf(q0.x, xj0, -q0.y * xi0);
            my[p0.z ^ rsw] = fmaf(q0.w, xj1,  q0.z * xi1);
            my[p0.w ^ rsw] = fmaf(q0.z, xj1, -q0.w * xi1);
            my[p1.x ^ rsw] = fmaf(q1.y, xj2,  q1.x * xi2);
            my[p1.y ^ rsw] = fmaf(q1.x, xj2, -q1.y * xi2);
            my[p1.z ^ rsw] = fmaf(q1.w, xj3,  q1.z * xi3);
            my[p1.w ^ rsw] = fmaf(q1.z, xj3, -q1.w * xi3);
        }
    }

    // --- cold generic path: y = y @ r_matrix (own row only, no barrier) ---
    if (bad) {
        const int rbase = tid * HD;
        const int rsw   = tid & 31;
        float zl[HD]; // local memory (unroll 1) -> no hot-path registers
        #pragma unroll 1
        for (int c = 0; c < HD; c++) {
            float acc = 0.0f;
            #pragma unroll 1
            for (int k = 0; k < HD; k++)
                acc = fmaf(buf[rbase + (k ^ rsw)], __ldg(&r_matrix[k * HD + c]), acc);
            zl[c] = acc;
        }
        #pragma unroll 1
        for (int c = 0; c < HD; c++)
            buf[rbase + (c ^ rsw)] = zl[c];
    }
    __syncthreads();

    // --- fused RoPE + store, specialized per warp (uniform switch) ---
    float4* __restrict__ op = reinterpret_cast<float4*>(out) + (elem_base >> 2);
    {
        const int l5  = tid & 31;
        const int sub = l5 >> 3;          // 0..3
        const int qp  = l5 & 7;           // freq-quad 0..7
        switch (tid >> 5) {
            case 0: epilogue<0>(buf4, cosq, sinq, op, sub, qp); break;
            case 1: epilogue<1>(buf4, cosq, sinq, op, sub, qp); break;
            case 2: epilogue<2>(buf4, cosq, sinq, op, sub, qp); break;
            default: epilogue<3>(buf4, cosq, sinq, op, sub, qp); break;
        }
    }
}

// ---------------------------------------------------------------------------
extern "C" void kernel_launch(void* const* d_in, const int* in_sizes, int n_in,
                              void* d_out, int out_size) {
    const float* x        = (const float*)d_in[0];
    const float* thetas   = (const float*)d_in[1];
    const float* r_pairs  = (const float*)d_in[2];
    const float* t_scale  = (const float*)d_in[3];
    // d_in[4] = n_rots_scale (unused by the reference)
    const float* r_matrix = (const float*)d_in[5];
    const float* inv_freq = (const float*)d_in[6];
    float* out = (float*)d_out;

    k_setup<<<1, 256>>>(thetas, r_pairs, t_scale, r_matrix);

    int nblocks = ROWS / TPB; // 4096
    k_main<<<nblocks, TPB>>>(x, r_matrix, inv_freq, out);
}

// round 17
// speedup vs baseline: 1.1842x; 1.0740x over previous
#include <cuda_runtime.h>
#include <cuda_bf16.h>
#include <math.h>

// Problem constants (fixed by the reference)
#define BB 8
#define SS 4096
#define DD 1024
#define HH 16
#define HD 64
#define NR 32
#define NFREQ 32            // HD/2
#define ROWS (BB * SS * HH) // 524288
#define TPB 128
#define NCMAX 32

// Static device scratch. chunk ch occupies entries [ch*8, ch*8+8):
// (i0,j0,i1,j1,i2,j2,i3,j3) / (c0,s0,c1,s1,c2,s2,c3,s3).
__device__ int    g_nc;
__device__ int    g_bad;
__device__ __align__(16) int   g_pair[NCMAX * 8];
__device__ __align__(16) float g_csab[NCMAX * 8];

// ---------------------------------------------------------------------------
// Setup: identity check + capacity-capped Kahn rotation scheduling (proven
// R16). Bit-identical to the sequential scan.
__global__ void k_setup(const float* __restrict__ thetas,
                        const float* __restrict__ r_pairs,
                        const float* __restrict__ theta_scale,
                        const float* __restrict__ rm) {
    __shared__ int si[NR], sj[NR];
    int t = threadIdx.x; // 256 threads

    int local = 0;
    const float4* __restrict__ rm4 = reinterpret_cast<const float4*>(rm);
    #pragma unroll
    for (int m = 0; m < 4; m++) {
        int e4 = t + m * 256;
        float4 v = __ldg(&rm4[e4]);
        int rrow = e4 >> 4, cc = (e4 & 15) << 2;
        if (v.x != ((rrow == cc + 0) ? 1.0f : 0.0f) ||
            v.y != ((rrow == cc + 1) ? 1.0f : 0.0f) ||
            v.z != ((rrow == cc + 2) ? 1.0f : 0.0f) ||
            v.w != ((rrow == cc + 3) ? 1.0f : 0.0f)) local = 1;
    }
    int bad = __syncthreads_or(local);
    if (t == 0) g_bad = bad;

    g_pair[t] = 0;
    g_csab[t] = (t & 1) ? 0.0f : 1.0f;

    int i = 0, j = 0;
    float cv = 1.0f, sv = 0.0f;
    if (t < NR) {
        i = (int)r_pairs[2 * t];
        j = (int)r_pairs[2 * t + 1];
        float th = thetas[t] * theta_scale[0];
        float s_, c_;
        sincosf(th, &s_, &c_);
        cv = c_;
        sv = (i == j) ? 0.0f : s_;
        si[t] = i; sj[t] = j;
    }
    __syncthreads();

    if (t < 32) {
        unsigned conf = 0;
        #pragma unroll
        for (int r = 0; r < NR; r++) {
            int ci = si[r], cj = sj[r];
            bool hit = (ci == i) | (ci == j) | (cj == i) | (cj == j);
            if (r < t && hit) conf |= (1u << r);
        }
        unsigned remaining = 0xFFFFFFFFu;
        int mych = 0, myslot = 0, ch = 0;
        while (remaining) {
            bool ready = ((remaining >> t) & 1u) && ((conf & remaining) == 0u);
            unsigned bal = __ballot_sync(0xFFFFFFFFu, ready);
            int rank = __popc(bal & ((1u << t) - 1u));
            bool sel = ready && (rank < 4);
            unsigned selb = __ballot_sync(0xFFFFFFFFu, sel);
            if (sel) { mych = ch; myslot = rank; }
            remaining &= ~selb;
            ch++;
        }
        if (t == 0) g_nc = ch;
        g_pair[mych * 8 + 2 * myslot]     = i;
        g_pair[mych * 8 + 2 * myslot + 1] = j;
        g_csab[mych * 8 + 2 * myslot]     = cv;
        g_csab[mych * 8 + 2 * myslot + 1] = sv;
    }
}

// ---------------------------------------------------------------------------
// XOR component permute; p is a literal after full unroll -> branches fold.
__device__ __forceinline__ float4 xperm(float4 v, int p) {
    float4 w = v;
    if (p & 1) w = make_float4(w.y, w.x, w.w, w.z);
    if (p & 2) w = make_float4(w.z, w.w, w.x, w.y);
    return w;
}

// Warp-autonomous main kernel. 128 threads/block, 128 rows (32 KB).
// Warp w owns rows 32w..32w+31 end-to-end: stage -> rotate -> RoPE+store.
// Only ONE block barrier (rotation schedule); everything else __syncwarp.
// Swizzled layout: element (row, col) at buf[row*64 + (col ^ (row & 31))].
__global__ void __launch_bounds__(TPB, 6)
k_main(const float* __restrict__ x,
       const float* __restrict__ r_matrix,
       const float* __restrict__ inv_freq,
       float* __restrict__ out) {
    __shared__ float  buf[TPB * HD];      // 32 KB, swizzled
    __shared__ float4 cosq[8][8];         // [s-group][freq-quad]
    __shared__ float4 sinq[8][8];
    __shared__ int4   ssij[2 * NCMAX];
    __shared__ float4 sscs[2 * NCMAX];

    const int tid = threadIdx.x;
    const int bid = blockIdx.x;
    const long long elem_base = (long long)bid * (TPB * HD);
    float4* __restrict__ buf4 = reinterpret_cast<float4*>(buf);

    const int w   = tid >> 5;
    const int l   = tid & 31;
    const int h   = l >> 4;          // half-warp
    const int q15 = l & 15;
    const int R   = w * 32;          // warp's first row

    const float2* __restrict__ xin2 =
        reinterpret_cast<const float2*>(x) + (elem_base >> 1);

    // ---- chunk 0 loads issued FIRST (8 LDG.64; cols split to make the
    //      swizzled scalar stores bank-conflict-free incl. col-bit5) ----
    float2 a0[4], a1[4];
    #pragma unroll
    for (int u = 0; u < 4; u++) {
        int idx = (R + 2 * u + h) * 32 + q15;
        a0[u] = __ldcs(&xin2[idx]);        // cols 2q15, 2q15+1
        a1[u] = __ldcs(&xin2[idx + 16]);   // cols 2q15+32, 2q15+33
    }

    // ---- in chunk-0 shadow: sched copy + per-warp cs tables ----
    if (tid < 2 * NCMAX) {
        ssij[tid] = reinterpret_cast<const int4*>(g_pair)[tid];
        sscs[tid] = reinterpret_cast<const float4*>(g_csab)[tid];
    }
    {
        // warp w, half h covers s-group 2w+h (rows R+16h..R+16h+15, one s)
        int s = (bid * 8 + 2 * w + h) & (SS - 1);
        float fs = (float)s;
        #pragma unroll
        for (int m = 0; m < 2; m++) {
            int k = q15 + 16 * m;
            float a = fs * __ldg(&inv_freq[k]);
            float sv, cv;
            sincosf(a, &sv, &cv);
            reinterpret_cast<float*>(&cosq[2 * w + h][k >> 2])[k & 3] = cv;
            reinterpret_cast<float*>(&sinq[2 * w + h][k >> 2])[k & 3] = sv;
        }
    }
    const int nc  = __ldg(&g_nc);
    const int bad = __ldg(&g_bad);
    __syncthreads();   // the ONLY block barrier: schedule visible to all warps

    // ---- staging: scalar STS, conflict-free; chunks of 4 its (MLP cap) ----
    const int c2 = 2 * q15;
    #pragma unroll
    for (int u = 0; u < 4; u++) {
        int rsw = 2 * u + h;
        float* bp = &buf[(R + rsw) * 64];
        bp[(c2 + 0)  ^ rsw] = a0[u].x;
        bp[(c2 + 1)  ^ rsw] = a0[u].y;
        bp[(c2 + 32) ^ rsw] = a1[u].x;
        bp[(c2 + 33) ^ rsw] = a1[u].y;
    }
    asm volatile("" ::: "memory");
    #pragma unroll
    for (int ch = 1; ch < 4; ch++) {
        float2 b0[4], b1[4];
        #pragma unroll
        for (int u = 0; u < 4; u++) {
            int it = ch * 4 + u;
            int idx = (R + 2 * it + h) * 32 + q15;
            b0[u] = __ldcs(&xin2[idx]);
            b1[u] = __ldcs(&xin2[idx + 16]);
        }
        #pragma unroll
        for (int u = 0; u < 4; u++) {
            int it = ch * 4 + u;
            int rsw = 2 * it + h;
            float* bp = &buf[(R + rsw) * 64];
            bp[(c2 + 0)  ^ rsw] = b0[u].x;
            bp[(c2 + 1)  ^ rsw] = b0[u].y;
            bp[(c2 + 32) ^ rsw] = b1[u].x;
            bp[(c2 + 33) ^ rsw] = b1[u].y;
        }
        asm volatile("" ::: "memory");
    }
    __syncwarp();      // warp's rows fully staged

    // ---- Givens rotations (lane l on row R+l = tid; conflict-free) ----
    {
        float* __restrict__ my = &buf[tid * HD];
        const int rsw = l;
        for (int ch = 0; ch < nc; ch++) {
            int4   p0 = ssij[2 * ch], p1 = ssij[2 * ch + 1];
            float4 q0 = sscs[2 * ch], q1 = sscs[2 * ch + 1];
            float xi0 = my[p0.x ^ rsw], xj0 = my[p0.y ^ rsw];
            float xi1 = my[p0.z ^ rsw], xj1 = my[p0.w ^ rsw];
            float xi2 = my[p1.x ^ rsw], xj2 = my[p1.y ^ rsw];
            float xi3 = my[p1.z ^ rsw], xj3 = my[p1.w ^ rsw];
            my[p0.x ^ rsw] = fmaf(q0.y, xj0,  q0.x * xi0);
            my[p0.y ^ rsw] = fmaf(q0.x, xj0, -q0.y * xi0);
            my[p0.z ^ rsw] = fmaf(q0.w, xj1,  q0.z * xi1);
            my[p0.w ^ rsw] = fmaf(q0.z, xj1, -q0.w * xi1);
            my[p1.x ^ rsw] = fmaf(q1.y, xj2,  q1.x * xi2);
            my[p1.y ^ rsw] = fmaf(q1.x, xj2, -q1.y * xi2);
            my[p1.z ^ rsw] = fmaf(q1.w, xj3,  q1.z * xi3);
            my[p1.w ^ rsw] = fmaf(q1.z, xj3, -q1.w * xi3);
        }
    }

    // ---- cold generic path: y = y @ r_matrix (own row only) ----
    if (bad) {
        const int rbase = tid * HD;
        const int rsw   = l;
        float zl[HD];
        #pragma unroll 1
        for (int c = 0; c < HD; c++) {
            float acc = 0.0f;
            #pragma unroll 1
            for (int k = 0; k < HD; k++)
                acc = fmaf(buf[rbase + (k ^ rsw)], __ldg(&r_matrix[k * HD + c]), acc);
            zl[c] = acc;
        }
        #pragma unroll 1
        for (int c = 0; c < HD; c++)
            buf[rbase + (c ^ rsw)] = zl[c];
    }
    __syncwarp();      // warp's rows fully rotated

    // ---- fused RoPE + store. Lane (h,q15): rows R+16h+it (it=0..15), all in
    //      ONE s-group -> cos/sin loop-invariant. Permute it&3 folds under
    //      unroll; ld0 = qA ^ (qp>>2) spreads LDS across all 8 bank-quads. ----
    float4* __restrict__ op = reinterpret_cast<float4*>(out) + (elem_base >> 2);
    {
        const int qp   = q15 & 7;
        const int half = q15 >> 3;
        const int p2   = qp >> 2;
        float4 cq = cosq[2 * w + h][qp];
        float4 sq = sinq[2 * w + h][qp];
        float4 A, B; // out = y0*A + y1*B : lo:(c,-s) hi:(s,c)
        A.x = half ? sq.x : cq.x;  B.x = half ? cq.x : -sq.x;
        A.y = half ? sq.y : cq.y;  B.y = half ? cq.y : -sq.y;
        A.z = half ? sq.z : cq.z;  B.z = half ? cq.z : -sq.z;
        A.w = half ? sq.w : cq.w;  B.w = half ? cq.w : -sq.w;

        #pragma unroll
        for (int it = 0; it < 16; it++) {
            int row  = R + 16 * h + it;
            int base = row * 16;
            int sig  = (it >> 2) ^ (4 * h);   // (rsw>>2)&7, rsw = 16h+it
            int qA   = (2 * qp) ^ sig;        // phys quad of logical quad 2qp
            int ld0  = qA ^ p2;               // bank diversifier
            float4 t0 = buf4[base + ld0];
            float4 t1 = buf4[base + (ld0 ^ 1)];
            float4 ra = p2 ? t1 : t0;         // = buf4[base+qA]
            float4 rb = p2 ? t0 : t1;
            float4 ya = xperm(ra, it & 3);    // y[8qp+0..3]
            float4 yb = xperm(rb, it & 3);    // y[8qp+4..7]
            float4 o;
            o.x = fmaf(ya.y, B.x, ya.x * A.x);
            o.y = fmaf(ya.w, B.y, ya.z * A.y);
            o.z = fmaf(yb.y, B.z, yb.x * A.z);
            o.w = fmaf(yb.w, B.w, yb.z * A.w);
            __stcs(&op[base + q15], o);
        }
    }
}

// ---------------------------------------------------------------------------
extern "C" void kernel_launch(void* const* d_in, const int* in_sizes, int n_in,
                              void* d_out, int out_size) {
    const float* x        = (const float*)d_in[0];
    const float* thetas   = (const float*)d_in[1];
    const float* r_pairs  = (const float*)d_in[2];
    const float* t_scale  = (const float*)d_in[3];
    // d_in[4] = n_rots_scale (unused by the reference)
    const float* r_matrix = (const float*)d_in[5];
    const float* inv_freq = (const float*)d_in[6];
    float* out = (float*)d_out;

    k_setup<<<1, 256>>>(thetas, r_pairs, t_scale, r_matrix);

    int nblocks = ROWS / TPB; // 4096
    k_main<<<nblocks, TPB>>>(x, r_matrix, inv_freq, out);
}